// round 2
// baseline (speedup 1.0000x reference)
#include <cuda_runtime.h>
#include <math_constants.h>

#define BN 4
#define TT 512
#define SS 512
#define IND 512
#define MD 256

// Scratch (allocation-free rule: __device__ globals)
__device__ float g_wq[BN * TT * MD];      // [b*T+t][d]
__device__ float g_uht[BN * MD * SS];     // [b][d][s]  (transposed uh)
__device__ float g_c[BN * TT * MD];       // [b*T+t][m]
__device__ float g_align_scratch[BN * TT * SS];  // fallback if out has no align region

__device__ __forceinline__ float tanhap(float x) {
    float y;
    asm("tanh.approx.f32 %0, %1;" : "=f"(y) : "f"(x));
    return y;
}

// ---------------------------------------------------------------------------
// proj_kernel: z=0 -> g_wq = inputs @ Wq^T            (M=2048, N=256, K=512)
//              z=1 -> g_uht[b][n][s] = mems @ Wc^T+bc (M=2048, N=256, K=256)
// 64x64 tile, 128 threads, 8x4 per thread, TK=8, double-buffered smem.
// ---------------------------------------------------------------------------
__global__ __launch_bounds__(128) void proj_kernel(
    const float* __restrict__ inputs, const float* __restrict__ mems,
    const float* __restrict__ Wq, const float* __restrict__ Wc,
    const float* __restrict__ bc)
{
    const int z = blockIdx.z;
    const float* A = z ? mems : inputs;
    const float* W = z ? Wc : Wq;
    const int K = z ? MD : IND;

    __shared__ float As[2][8][68];
    __shared__ float Bs[2][8][68];

    const int tid = threadIdx.x;
    const int bm = blockIdx.y * 64;
    const int bn = blockIdx.x * 64;
    const int lr = tid >> 1;
    const int lc = (tid & 1) * 4;
    const int tx = tid & 15, ty = tid >> 4;
    const int n0 = tx * 4, m0 = ty * 8;

    float acc[8][4];
#pragma unroll
    for (int i = 0; i < 8; i++)
#pragma unroll
        for (int j = 0; j < 4; j++) acc[i][j] = 0.f;

    const float* Arow = A + (bm + lr) * K + lc;
    const float* Wrow = W + (bn + lr) * K + lc;

    float4 a4 = *(const float4*)Arow;
    float4 b4 = *(const float4*)Wrow;
    As[0][lc + 0][lr] = a4.x; As[0][lc + 1][lr] = a4.y;
    As[0][lc + 2][lr] = a4.z; As[0][lc + 3][lr] = a4.w;
    Bs[0][lc + 0][lr] = b4.x; Bs[0][lc + 1][lr] = b4.y;
    Bs[0][lc + 2][lr] = b4.z; Bs[0][lc + 3][lr] = b4.w;
    __syncthreads();

    const int NT = K >> 3;
    int buf = 0;
    for (int t = 0; t < NT; t++) {
        const bool more = (t + 1 < NT);
        if (more) {
            a4 = *(const float4*)(Arow + (t + 1) * 8);
            b4 = *(const float4*)(Wrow + (t + 1) * 8);
        }
#pragma unroll
        for (int kk = 0; kk < 8; kk++) {
            float4 x0 = *(const float4*)&As[buf][kk][m0];
            float4 x1 = *(const float4*)&As[buf][kk][m0 + 4];
            float4 y  = *(const float4*)&Bs[buf][kk][n0];
            float am[8] = {x0.x, x0.y, x0.z, x0.w, x1.x, x1.y, x1.z, x1.w};
            float bb[4] = {y.x, y.y, y.z, y.w};
#pragma unroll
            for (int i = 0; i < 8; i++)
#pragma unroll
                for (int j = 0; j < 4; j++) acc[i][j] += am[i] * bb[j];
        }
        if (more) {
            const int nb = buf ^ 1;
            As[nb][lc + 0][lr] = a4.x; As[nb][lc + 1][lr] = a4.y;
            As[nb][lc + 2][lr] = a4.z; As[nb][lc + 3][lr] = a4.w;
            Bs[nb][lc + 0][lr] = b4.x; Bs[nb][lc + 1][lr] = b4.y;
            Bs[nb][lc + 2][lr] = b4.z; Bs[nb][lc + 3][lr] = b4.w;
        }
        __syncthreads();
        buf ^= 1;
    }

    if (z == 0) {
#pragma unroll
        for (int i = 0; i < 8; i++) {
            float4 r = make_float4(acc[i][0], acc[i][1], acc[i][2], acc[i][3]);
            *(float4*)&g_wq[(bm + m0 + i) * MD + bn + n0] = r;
        }
    } else {
        float bb[4];
#pragma unroll
        for (int j = 0; j < 4; j++) bb[j] = bc[bn + n0 + j];
#pragma unroll
        for (int i = 0; i < 8; i++) {
            const int m = bm + m0 + i;
            const int b = m >> 9;
            const int s = m & 511;
#pragma unroll
            for (int j = 0; j < 4; j++)
                g_uht[b * (MD * SS) + (bn + n0 + j) * SS + s] = acc[i][j] + bb[j];
        }
    }
}

// ---------------------------------------------------------------------------
// align_kernel: grid (s-chunk, t-tile, b). One 128-s chunk x 16-t per block.
// Early-exits if the whole chunk is masked (load balance across the chip).
// Writes RAW scores to pa (masked columns handled by softctx).
// smem: uh chunk [256 d][128 s] 128KB | wq [16][256] 16KB | v 1KB
// ---------------------------------------------------------------------------
__global__ __launch_bounds__(256) void align_kernel(
    const int* __restrict__ mem_masks, const float* __restrict__ v,
    float* __restrict__ pa)
{
    const int b = blockIdx.z;
    const int t0 = blockIdx.y * 16;
    const int c = blockIdx.x;
    const int len = mem_masks[b];
    if (c * 128 >= len) return;

    extern __shared__ float sh[];
    float* uh_sh = sh;                 // [256][128]
    float* wq_sh = sh + 256 * 128;     // [16][256]
    float* v_sh  = wq_sh + 16 * 256;   // [256]

    const int tid = threadIdx.x;
    const int lane = tid & 31;
    const int warp = tid >> 5;

    {
        const float* src = g_wq + (b * TT + t0) * MD;
        for (int i = tid; i < (16 * 256) / 4; i += 256)
            *(float4*)&wq_sh[i * 4] = *(const float4*)&src[i * 4];
        if (tid < 64)
            *(float4*)&v_sh[tid * 4] = *(const float4*)&v[tid * 4];
        const float* usrc = g_uht + b * (MD * SS) + c * 128;
        for (int i = tid; i < 256 * 32; i += 256) {
            const int d = i >> 5, g = i & 31;
            *(float4*)&uh_sh[d * 128 + g * 4] =
                *(const float4*)&usrc[d * SS + g * 4];
        }
    }
    __syncthreads();

    const int ta = warp * 2;
    const float* wq0 = wq_sh + ta * 256;
    const float* wq1 = wq0 + 256;
    const int sl = lane * 4;
    float4 a0 = make_float4(0.f, 0.f, 0.f, 0.f);
    float4 a1 = make_float4(0.f, 0.f, 0.f, 0.f);
#pragma unroll 4
    for (int d = 0; d < 256; d++) {
        float4 u = *(float4*)&uh_sh[d * 128 + sl];
        float w0 = wq0[d], w1 = wq1[d], vd = v_sh[d];
        a0.x += vd * tanhap(u.x + w0);
        a0.y += vd * tanhap(u.y + w0);
        a0.z += vd * tanhap(u.z + w0);
        a0.w += vd * tanhap(u.w + w0);
        a1.x += vd * tanhap(u.x + w1);
        a1.y += vd * tanhap(u.y + w1);
        a1.z += vd * tanhap(u.z + w1);
        a1.w += vd * tanhap(u.w + w1);
    }
    const int sg = c * 128 + sl;
    *(float4*)&pa[(b * TT + t0 + ta) * SS + sg] = a0;
    *(float4*)&pa[(b * TT + t0 + ta + 1) * SS + sg] = a1;
}

// ---------------------------------------------------------------------------
// softctx_kernel: one block per (b, 16-t tile).
//   load raw scores (guarded by len), masked softmax, write p (all 512 cols),
//   then context c = P @ mems.
// smem: mems chunk [128][256] 128KB | p [16][512] 32KB
// ---------------------------------------------------------------------------
__global__ __launch_bounds__(256) void softctx_kernel(
    const float* __restrict__ mems, const int* __restrict__ mem_masks,
    float* __restrict__ pa)
{
    extern __shared__ float sh[];
    float* mem_sh = sh;                // [128][256]
    float* al_sh  = sh + 128 * 256;    // [16][512]

    const int tid = threadIdx.x;
    const int lane = tid & 31;
    const int warp = tid >> 5;
    const int b = blockIdx.x >> 5;
    const int t0 = (blockIdx.x & 31) * 16;
    const int len = mem_masks[b];
    const float NEG = -CUDART_INF_F;

    for (int i = tid; i < 16 * 512; i += 256) {
        const int t = i >> 9, s = i & 511;
        al_sh[i] = (s < len) ? pa[(b * TT + t0 + t) * SS + s] : NEG;
    }
    __syncthreads();

    // masked softmax: warp handles 2 rows
    for (int r = 0; r < 2; r++) {
        const int t = warp * 2 + r;
        float* row = al_sh + t * 512;
        float mx = NEG;
#pragma unroll
        for (int k = 0; k < 16; k++) mx = fmaxf(mx, row[lane + k * 32]);
#pragma unroll
        for (int o = 16; o; o >>= 1) mx = fmaxf(mx, __shfl_xor_sync(~0u, mx, o));
        float e[16];
        float sum = 0.f;
#pragma unroll
        for (int k = 0; k < 16; k++) {
            const int s = lane + k * 32;
            const float val = (s < len) ? __expf(row[s] - mx) : 0.f;
            e[k] = val;
            sum += val;
        }
#pragma unroll
        for (int o = 16; o; o >>= 1) sum += __shfl_xor_sync(~0u, sum, o);
        const float inv = 1.0f / sum;
#pragma unroll
        for (int k = 0; k < 16; k++) {
            const int s = lane + k * 32;
            const float p = e[k] * inv;
            row[s] = p;
            pa[(b * TT + t0 + t) * SS + s] = p;
        }
    }

    // context
    float cc[4][4];
#pragma unroll
    for (int i = 0; i < 4; i++)
#pragma unroll
        for (int j = 0; j < 4; j++) cc[i][j] = 0.f;

    const int tq = (tid >> 6) * 4;
    const int m0 = (tid & 63) * 4;
    const int nch = (len + 127) >> 7;

    for (int c = 0; c < nch; c++) {
        __syncthreads();
        {
            const float* src = mems + b * (SS * MD) + c * 128 * MD;
            for (int i = tid; i < (128 * 256) / 4; i += 256)
                *(float4*)&mem_sh[i * 4] = *(const float4*)&src[i * 4];
        }
        __syncthreads();
#pragma unroll 2
        for (int s2 = 0; s2 < 128; s2++) {
            float4 mm = *(float4*)&mem_sh[s2 * 256 + m0];
            const int s = c * 128 + s2;
            const float p0 = al_sh[(tq + 0) * 512 + s];
            const float p1 = al_sh[(tq + 1) * 512 + s];
            const float p2 = al_sh[(tq + 2) * 512 + s];
            const float p3 = al_sh[(tq + 3) * 512 + s];
            cc[0][0] += p0 * mm.x; cc[0][1] += p0 * mm.y;
            cc[0][2] += p0 * mm.z; cc[0][3] += p0 * mm.w;
            cc[1][0] += p1 * mm.x; cc[1][1] += p1 * mm.y;
            cc[1][2] += p1 * mm.z; cc[1][3] += p1 * mm.w;
            cc[2][0] += p2 * mm.x; cc[2][1] += p2 * mm.y;
            cc[2][2] += p2 * mm.z; cc[2][3] += p2 * mm.w;
            cc[3][0] += p3 * mm.x; cc[3][1] += p3 * mm.y;
            cc[3][2] += p3 * mm.z; cc[3][3] += p3 * mm.w;
        }
    }
#pragma unroll
    for (int i = 0; i < 4; i++) {
        float4 r = make_float4(cc[i][0], cc[i][1], cc[i][2], cc[i][3]);
        *(float4*)&g_c[(b * TT + t0 + tq + i) * MD + m0] = r;
    }
}

// ---------------------------------------------------------------------------
// out_kernel: attn_h = concat(c, inputs) @ Wout^T + bout
// M=2048, N=512, K=768. 64x64 tile, 128 threads, double-buffered.
// ---------------------------------------------------------------------------
__global__ __launch_bounds__(128) void out_kernel(
    const float* __restrict__ inputs, const float* __restrict__ Wout,
    const float* __restrict__ bout, float* __restrict__ out)
{
    __shared__ float As[2][8][68];
    __shared__ float Bs[2][8][68];

    const int tid = threadIdx.x;
    const int bm = blockIdx.y * 64;
    const int bn = blockIdx.x * 64;
    const int lr = tid >> 1;
    const int lc = (tid & 1) * 4;
    const int tx = tid & 15, ty = tid >> 4;
    const int n0 = tx * 4, m0 = ty * 8;

    float acc[8][4];
#pragma unroll
    for (int i = 0; i < 8; i++)
#pragma unroll
        for (int j = 0; j < 4; j++) acc[i][j] = 0.f;

    const float* crow = g_c + (bm + lr) * MD;
    const float* irow = inputs + (bm + lr) * IND;
    const float* Wrow = Wout + (bn + lr) * 768 + lc;

    auto loadA = [&](int k0) -> float4 {
        const int k = k0 + lc;
        if (k < 256) return *(const float4*)(crow + k);
        return *(const float4*)(irow + (k - 256));
    };

    float4 a4 = loadA(0);
    float4 b4 = *(const float4*)Wrow;
    As[0][lc + 0][lr] = a4.x; As[0][lc + 1][lr] = a4.y;
    As[0][lc + 2][lr] = a4.z; As[0][lc + 3][lr] = a4.w;
    Bs[0][lc + 0][lr] = b4.x; Bs[0][lc + 1][lr] = b4.y;
    Bs[0][lc + 2][lr] = b4.z; Bs[0][lc + 3][lr] = b4.w;
    __syncthreads();

    const int NT = 768 / 8;
    int buf = 0;
    for (int t = 0; t < NT; t++) {
        const bool more = (t + 1 < NT);
        if (more) {
            a4 = loadA((t + 1) * 8);
            b4 = *(const float4*)(Wrow + (t + 1) * 8);
        }
#pragma unroll
        for (int kk = 0; kk < 8; kk++) {
            float4 x0 = *(const float4*)&As[buf][kk][m0];
            float4 x1 = *(const float4*)&As[buf][kk][m0 + 4];
            float4 y  = *(const float4*)&Bs[buf][kk][n0];
            float am[8] = {x0.x, x0.y, x0.z, x0.w, x1.x, x1.y, x1.z, x1.w};
            float bb[4] = {y.x, y.y, y.z, y.w};
#pragma unroll
            for (int i = 0; i < 8; i++)
#pragma unroll
                for (int j = 0; j < 4; j++) acc[i][j] += am[i] * bb[j];
        }
        if (more) {
            const int nb = buf ^ 1;
            As[nb][lc + 0][lr] = a4.x; As[nb][lc + 1][lr] = a4.y;
            As[nb][lc + 2][lr] = a4.z; As[nb][lc + 3][lr] = a4.w;
            Bs[nb][lc + 0][lr] = b4.x; Bs[nb][lc + 1][lr] = b4.y;
            Bs[nb][lc + 2][lr] = b4.z; Bs[nb][lc + 3][lr] = b4.w;
        }
        __syncthreads();
        buf ^= 1;
    }

    float4 bias = *(const float4*)(bout + bn + n0);
#pragma unroll
    for (int i = 0; i < 8; i++) {
        float4 r = make_float4(acc[i][0] + bias.x, acc[i][1] + bias.y,
                               acc[i][2] + bias.z, acc[i][3] + bias.w);
        *(float4*)&out[(bm + m0 + i) * IND + bn + n0] = r;
    }
}

// ---------------------------------------------------------------------------
extern "C" void kernel_launch(void* const* d_in, const int* in_sizes, int n_in,
                              void* d_out, int out_size)
{
    const float* inputs    = (const float*)d_in[0];
    const float* mems      = (const float*)d_in[1];
    const int*   mem_masks = (const int*)d_in[2];
    const float* Wq        = (const float*)d_in[3];
    const float* Wc        = (const float*)d_in[4];
    const float* bc        = (const float*)d_in[5];
    const float* v         = (const float*)d_in[6];
    const float* Wout      = (const float*)d_in[7];
    const float* bout      = (const float*)d_in[8];

    float* out = (float*)d_out;
    float* pa;
    if (out_size >= BN * TT * IND + BN * TT * SS) {
        pa = out + BN * TT * IND;  // write align in-place in the output
    } else {
        cudaGetSymbolAddress((void**)&pa, g_align_scratch);
    }

    const size_t SMEM_ALIGN = (size_t)(256 * 128 + 16 * 256 + 256) * sizeof(float);
    const size_t SMEM_SOFT  = (size_t)(128 * 256 + 16 * 512) * sizeof(float);
    cudaFuncSetAttribute(align_kernel,
                         cudaFuncAttributeMaxDynamicSharedMemorySize, (int)SMEM_ALIGN);
    cudaFuncSetAttribute(softctx_kernel,
                         cudaFuncAttributeMaxDynamicSharedMemorySize, (int)SMEM_SOFT);

    proj_kernel<<<dim3(4, 32, 2), 128>>>(inputs, mems, Wq, Wc, bc);
    align_kernel<<<dim3(4, 32, 4), 256, SMEM_ALIGN>>>(mem_masks, v, pa);
    softctx_kernel<<<128, 256, SMEM_SOFT>>>(mems, mem_masks, pa);
    out_kernel<<<dim3(8, 32), 128>>>(inputs, Wout, bout, out);
}